// round 16
// baseline (speedup 1.0000x reference)
#include <cuda_runtime.h>
#include <cuda_bf16.h>
#include <cuda_fp16.h>

#define CN0 262144
#define CN1 131072
#define CN2 65536
#define CE0 2097152
#define CE1 1048576
#define CIN 128
#define CH  32
#define CEPS 1e-12f
#define BSTRIDE 68

typedef unsigned int uint;

// ---- scratch (device globals; referenced from DEVICE code only) ----
__device__ float  g_r0[(size_t)CN1 * CH];     // x[:N1] @ wr0^T (fp32 root path)
__device__ float  g_h [(size_t)CN1 * CH];     // layer-0 out (fp32 root path)
__device__ __half g_y0h[(size_t)CN0 * CH];    // x @ wl0^T (fp16 gather table)
__device__ __half g_hh [(size_t)CN1 * CH];    // h (fp16 gather table)

__device__ __nv_bfloat16 g_whi[64 * CIN];
__device__ __nv_bfloat16 g_wlo[64 * CIN];

__device__ int g_cnt0[CN1];
__device__ int g_cur0[CN1];                 // scan writes START; bucket bumps to END
__device__ int g_eid0[CE0];

__device__ int g_cnt1[CN2];
__device__ int g_cur1[CN2];
__device__ int g_eid1[CE1];

__device__ int g_tot[2];

__device__ __forceinline__ uint pkbf(float a, float b) {
    __nv_bfloat162 t = __halves2bfloat162(__float2bfloat16(a), __float2bfloat16(b));
    return *reinterpret_cast<uint*>(&t);
}
__device__ __forceinline__ void mma_bf16(float* d, const uint* a, uint b0, uint b1) {
    asm volatile(
        "mma.sync.aligned.m16n8k16.row.col.f32.bf16.bf16.f32 "
        "{%0,%1,%2,%3}, {%4,%5,%6,%7}, {%8,%9}, {%0,%1,%2,%3};"
        : "+f"(d[0]), "+f"(d[1]), "+f"(d[2]), "+f"(d[3])
        : "r"(a[0]), "r"(a[1]), "r"(a[2]), "r"(a[3]), "r"(b0), "r"(b1));
}
__device__ __forceinline__ void acc_h4(float4& acc, uint2 u) {
    __half2 h0 = *reinterpret_cast<__half2*>(&u.x);
    __half2 h1 = *reinterpret_cast<__half2*>(&u.y);
    float2 a = __half22float2(h0);
    float2 b = __half22float2(h1);
    acc.x += a.x; acc.y += a.y; acc.z += b.x; acc.w += b.y;
}

// ---- one 128-row GEMM tile body (weights staged by caller) ----
__device__ __forceinline__ void gemm_tile_body(
    int tile, const uint* sbh, const uint* sbl, const float* __restrict__ x)
{
    int tid = threadIdx.x;
    int wid = tid >> 5, lane = tid & 31;
    int mrow = lane >> 2;
    int c = lane & 3;
    int nl = lane >> 2;

    int row0 = tile * 128 + wid * 16 + mrow;
    const float2* x2 = (const float2*)x;
    size_t base0 = (size_t)row0 * 64 + c;
    size_t base1 = base0 + 8 * 64;

    float d[8][4];
    #pragma unroll
    for (int n = 0; n < 8; n++)
        #pragma unroll
        for (int j = 0; j < 4; j++) d[n][j] = 0.f;

    #pragma unroll
    for (int ks = 0; ks < 8; ks++) {
        float2 p0 = __ldg(&x2[base0 + ks * 8]);
        float2 p1 = __ldg(&x2[base1 + ks * 8]);
        float2 p2 = __ldg(&x2[base0 + ks * 8 + 4]);
        float2 p3 = __ldg(&x2[base1 + ks * 8 + 4]);

        uint ah[4], al[4];
        ah[0] = pkbf(p0.x, p0.y);
        ah[1] = pkbf(p1.x, p1.y);
        ah[2] = pkbf(p2.x, p2.y);
        ah[3] = pkbf(p3.x, p3.y);
        {
            __nv_bfloat162 h0 = *(__nv_bfloat162*)&ah[0];
            __nv_bfloat162 h1 = *(__nv_bfloat162*)&ah[1];
            __nv_bfloat162 h2 = *(__nv_bfloat162*)&ah[2];
            __nv_bfloat162 h3 = *(__nv_bfloat162*)&ah[3];
            al[0] = pkbf(p0.x - __bfloat162float(h0.x), p0.y - __bfloat162float(h0.y));
            al[1] = pkbf(p1.x - __bfloat162float(h1.x), p1.y - __bfloat162float(h1.y));
            al[2] = pkbf(p2.x - __bfloat162float(h2.x), p2.y - __bfloat162float(h2.y));
            al[3] = pkbf(p3.x - __bfloat162float(h3.x), p3.y - __bfloat162float(h3.y));
        }

        #pragma unroll
        for (int n = 0; n < 8; n++) {
            int bidx = (n * 8 + nl) * BSTRIDE + ks * 8 + c;
            uint bh0 = sbh[bidx], bh1 = sbh[bidx + 4];
            uint bl0 = sbl[bidx], bl1 = sbl[bidx + 4];
            mma_bf16(d[n], ah, bh0, bh1);
            mma_bf16(d[n], al, bh0, bh1);
            mma_bf16(d[n], ah, bl0, bl1);
        }
    }

    int rA = row0;
    int rB = row0 + 8;
    #pragma unroll
    for (int n = 0; n < 8; n++) {
        int col = (n & 3) * 8 + c * 2;
        if (n < 4) {
            *(__half2*)(g_y0h + (size_t)rA * CH + col) = __floats2half2_rn(d[n][0], d[n][1]);
            *(__half2*)(g_y0h + (size_t)rB * CH + col) = __floats2half2_rn(d[n][2], d[n][3]);
        } else if (rA < CN1) {
            *(float2*)(g_r0 + (size_t)rA * CH + col) = make_float2(d[n][0], d[n][1]);
            *(float2*)(g_r0 + (size_t)rB * CH + col) = make_float2(d[n][2], d[n][3]);
        }
    }
}

__device__ __forceinline__ void stage_weights(uint* sbh, uint* sbl)
{
    const uint* whi = (const uint*)g_whi;
    const uint* wlo = (const uint*)g_wlo;
    #pragma unroll
    for (int c = threadIdx.x; c < 4096; c += 256) {
        int r = c >> 6, k = c & 63;
        sbh[r * BSTRIDE + k] = __ldg(whi + c);
        sbl[r * BSTRIDE + k] = __ldg(wlo + c);
    }
    __syncthreads();
}

// ============================================================
// init: blocks [0,192) zero cnt0/cnt1 + g_tot,
//       blocks [192,224) split W into bf16 hi/lo.
// ============================================================
__global__ __launch_bounds__(256) void init_kernel(
    const float* __restrict__ wl0, const float* __restrict__ wr0)
{
    int blk = blockIdx.x;
    if (blk < 192) {
        int t = blk * 256 + threadIdx.x;          // 49152 int4 slots
        const int4 z = make_int4(0, 0, 0, 0);
        if (t < 32768) ((int4*)g_cnt0)[t] = z;
        else           ((int4*)g_cnt1)[t - 32768] = z;
        if (blk == 0 && threadIdx.x < 2) g_tot[threadIdx.x] = 0;
    } else {
        int i = (blk - 192) * 256 + threadIdx.x;  // 8192 weights
        float v = (i < 32 * CIN) ? wl0[i] : wr0[i - 32 * CIN];
        __nv_bfloat16 h = __float2bfloat16(v);
        g_whi[i] = h;
        g_wlo[i] = __float2bfloat16(v - __bfloat162float(h));
    }
}

// ============================================================
// histgemm: odd blocks hist (1024 blocks x 3 chunks = 3072),
// even blocks gemm tiles [0,1024).
// ============================================================
__global__ __launch_bounds__(256) void histgemm_kernel(
    const int* __restrict__ tgt0, const int* __restrict__ tgt1,
    const float* __restrict__ x)
{
    __shared__ uint sbh[64 * BSTRIDE];
    __shared__ uint sbl[64 * BSTRIDE];
    int blk = blockIdx.x;
    int tid = threadIdx.x;

    if (blk & 1) {
        int bi = blk >> 1;                    // 0..1023
        #pragma unroll
        for (int j = 0; j < 3; j++) {
            int u = bi + j * 1024;            // 0..3071
            const int* tgt; int* cnt; int eb;
            if (u < 2048) { tgt = tgt0; cnt = g_cnt0; eb = u; }
            else          { tgt = tgt1; cnt = g_cnt1; eb = u - 2048; }
            int b = (eb * 256 + tid) * 4;
            int4 t = __ldg((const int4*)(tgt + b));
            atomicAdd(&cnt[t.x], 1);
            atomicAdd(&cnt[t.y], 1);
            atomicAdd(&cnt[t.z], 1);
            atomicAdd(&cnt[t.w], 1);
        }
        return;
    }
    stage_weights(sbh, sbl);
    gemm_tile_body(blk >> 1, sbh, sbl, x);
}

// ============================================================
// scan_both: tile-local scan + bump-alloc; START -> cur.
// ============================================================
__global__ __launch_bounds__(256) void scan_both_kernel()
{
    int blk = blockIdx.x;
    const int* cnt;
    int* cur;
    int layer, tile;
    if (blk < 128) { cnt = g_cnt0; cur = g_cur0; layer = 0; tile = blk; }
    else           { cnt = g_cnt1; cur = g_cur1; layer = 1; tile = blk - 128; }

    __shared__ int wsum[8];
    __shared__ int sbase;
    int tid = threadIdx.x;
    int base = tile * 1024 + tid * 4;
    int4 c = __ldg((const int4*)(cnt + base));
    int s1 = c.x + c.y, s2 = s1 + c.z, s3 = s2 + c.w;

    int lane = tid & 31, w = tid >> 5;
    int v = s3;
    #pragma unroll
    for (int o = 1; o < 32; o <<= 1) {
        int t = __shfl_up_sync(0xffffffffu, v, o);
        if (lane >= o) v += t;
    }
    int thr_excl = v - s3;
    if (lane == 31) wsum[w] = v;
    __syncthreads();
    if (w == 0) {
        int ws = (lane < 8) ? wsum[lane] : 0;
        #pragma unroll
        for (int o = 1; o < 8; o <<= 1) {
            int t = __shfl_up_sync(0xffffffffu, ws, o);
            if (lane >= o) ws += t;
        }
        if (lane < 8) wsum[lane] = ws;
        if (lane == 7) sbase = atomicAdd(&g_tot[layer], ws);
    }
    __syncthreads();

    int gb = sbase + ((w == 0) ? 0 : wsum[w - 1]) + thr_excl;
    int4 o4;
    o4.x = gb; o4.y = gb + c.x; o4.z = gb + s1; o4.w = gb + s2;
    *(int4*)(cur + base) = o4;
}

// ============================================================
// bucket0gemm: odd blocks bucket layer0 (1024 x 2 chunks = 2048),
// even blocks gemm tiles [1024,2048).
// ============================================================
__global__ __launch_bounds__(256) void bucket0gemm_kernel(
    const int* __restrict__ src0, const int* __restrict__ tgt0,
    const float* __restrict__ x)
{
    __shared__ uint sbh[64 * BSTRIDE];
    __shared__ uint sbl[64 * BSTRIDE];
    int blk = blockIdx.x;
    int tid = threadIdx.x;

    if (blk & 1) {
        int bi = blk >> 1;                    // 0..1023
        #pragma unroll
        for (int j = 0; j < 2; j++) {
            int eb = bi + j * 1024;           // 0..2047
            int b = (eb * 256 + tid) * 4;
            int4 t = __ldg((const int4*)(tgt0 + b));
            int4 s = __ldg((const int4*)(src0 + b));
            int pos0 = atomicAdd(&g_cur0[t.x], 1);
            int pos1 = atomicAdd(&g_cur0[t.y], 1);
            int pos2 = atomicAdd(&g_cur0[t.z], 1);
            int pos3 = atomicAdd(&g_cur0[t.w], 1);
            g_eid0[pos0] = s.x;
            g_eid0[pos1] = s.y;
            g_eid0[pos2] = s.z;
            g_eid0[pos3] = s.w;
        }
        return;
    }
    stage_weights(sbh, sbl);
    gemm_tile_body(1024 + (blk >> 1), sbh, sbl, x);
}

// ============================================================
// aggfin0bucket1: grid = 512*33.
//   blk%33==32 -> bucket layer1 (bi = blk/33, chunks bi & bi+512)
//   else       -> aggfin0 row-block (blk/33)*32 + blk%33  (16384)
// ============================================================
__global__ __launch_bounds__(256) void aggfin0bucket1_kernel(
    const int* __restrict__ src1, const int* __restrict__ tgt1,
    const float* __restrict__ bias)
{
    int blk = blockIdx.x;
    int tid = threadIdx.x;
    int m = blk % 33;

    if (m == 32) {
        int bi = blk / 33;                    // 0..511
        #pragma unroll
        for (int j = 0; j < 2; j++) {
            int eb = bi + j * 512;            // 0..1023
            int b = (eb * 256 + tid) * 4;
            int4 t = __ldg((const int4*)(tgt1 + b));
            int4 s = __ldg((const int4*)(src1 + b));
            int pos0 = atomicAdd(&g_cur1[t.x], 1);
            int pos1 = atomicAdd(&g_cur1[t.y], 1);
            int pos2 = atomicAdd(&g_cur1[t.z], 1);
            int pos3 = atomicAdd(&g_cur1[t.w], 1);
            g_eid1[pos0] = s.x;
            g_eid1[pos1] = s.y;
            g_eid1[pos2] = s.z;
            g_eid1[pos3] = s.w;
        }
        return;
    }

    int rb = (blk / 33) * 32 + m;             // 0..16383
    int lane = tid & 31;
    int row = rb * 8 + (tid >> 5);
    int g = lane >> 3;
    int f4 = lane & 7;

    int cnt = __ldg(g_cnt0 + row);
    int start = __ldg(g_cur0 + row) - cnt;    // cur = end after bucket0

    float4 acc = make_float4(0.f, 0.f, 0.f, 0.f);
    int i = g;
    for (; i + 12 < cnt; i += 16) {
        int s0 = __ldg(g_eid0 + start + i);
        int s1 = __ldg(g_eid0 + start + i + 4);
        int s2 = __ldg(g_eid0 + start + i + 8);
        int s3 = __ldg(g_eid0 + start + i + 12);
        uint2 u0 = __ldg((const uint2*)(g_y0h + (size_t)s0 * CH) + f4);
        uint2 u1 = __ldg((const uint2*)(g_y0h + (size_t)s1 * CH) + f4);
        uint2 u2 = __ldg((const uint2*)(g_y0h + (size_t)s2 * CH) + f4);
        uint2 u3 = __ldg((const uint2*)(g_y0h + (size_t)s3 * CH) + f4);
        acc_h4(acc, u0); acc_h4(acc, u1); acc_h4(acc, u2); acc_h4(acc, u3);
    }
    for (; i < cnt; i += 4) {
        int s = __ldg(g_eid0 + start + i);
        uint2 u = __ldg((const uint2*)(g_y0h + (size_t)s * CH) + f4);
        acc_h4(acc, u);
    }
    #pragma unroll
    for (int o = 8; o <= 16; o <<= 1) {
        acc.x += __shfl_xor_sync(0xffffffffu, acc.x, o);
        acc.y += __shfl_xor_sync(0xffffffffu, acc.y, o);
        acc.z += __shfl_xor_sync(0xffffffffu, acc.z, o);
        acc.w += __shfl_xor_sync(0xffffffffu, acc.w, o);
    }

    float inv = 1.f / (float)max(cnt, 1);
    float4 b = __ldg((const float4*)bias + f4);
    float4 r = __ldg((const float4*)(g_r0 + (size_t)row * CH) + f4);

    float4 v;
    v.x = fmaf(acc.x, inv, b.x) + r.x;
    v.y = fmaf(acc.y, inv, b.y) + r.y;
    v.z = fmaf(acc.z, inv, b.z) + r.z;
    v.w = fmaf(acc.w, inv, b.w) + r.w;

    float s = v.x * v.x + v.y * v.y + v.z * v.z + v.w * v.w;
    s += __shfl_xor_sync(0xffffffffu, s, 1);
    s += __shfl_xor_sync(0xffffffffu, s, 2);
    s += __shfl_xor_sync(0xffffffffu, s, 4);
    float rinv = 1.f / fmaxf(sqrtf(s), CEPS);

    float4 o;
    o.x = fmaxf(v.x * rinv, 0.f);
    o.y = fmaxf(v.y * rinv, 0.f);
    o.z = fmaxf(v.z * rinv, 0.f);
    o.w = fmaxf(v.w * rinv, 0.f);
    if (g == 0) {
        ((float4*)(g_h + (size_t)row * CH))[f4] = o;
        uint2 hp;
        __half2 h0 = __floats2half2_rn(o.x, o.y);
        __half2 h1 = __floats2half2_rn(o.z, o.w);
        hp.x = *reinterpret_cast<uint*>(&h0);
        hp.y = *reinterpret_cast<uint*>(&h1);
        ((uint2*)(g_hh + (size_t)row * CH))[f4] = hp;
    }
}

// ============================================================
// aggfin1: warp per target row; fp16 gather of hh, fp32 root
// from g_h, per-lane matvec wl1/wr1, L2norm -> out
// ============================================================
__global__ __launch_bounds__(256) void aggfin1_kernel(
    const float* __restrict__ bl1,
    const float* __restrict__ wl1, const float* __restrict__ wr1,
    float* __restrict__ out)
{
    __shared__ float swl[CH * 33];
    __shared__ float swr[CH * 33];
    __shared__ float smean[8][CH];
    __shared__ float sroot[8][CH];

    int tid = threadIdx.x;
    for (int i = tid; i < CH * CH; i += 256) {
        int j = i >> 5, d = i & 31;
        swl[j * 33 + d] = __ldg(wl1 + i);
        swr[j * 33 + d] = __ldg(wr1 + i);
    }
    __syncthreads();

    int lane = tid & 31, w = tid >> 5;
    int row = blockIdx.x * 8 + w;
    int g = lane >> 3;
    int f4 = lane & 7;

    int cnt = __ldg(g_cnt1 + row);
    int start = __ldg(g_cur1 + row) - cnt;

    float4 acc = make_float4(0.f, 0.f, 0.f, 0.f);
    int i = g;
    for (; i + 12 < cnt; i += 16) {
        int s0 = __ldg(g_eid1 + start + i);
        int s1 = __ldg(g_eid1 + start + i + 4);
        int s2 = __ldg(g_eid1 + start + i + 8);
        int s3 = __ldg(g_eid1 + start + i + 12);
        uint2 u0 = __ldg((const uint2*)(g_hh + (size_t)s0 * CH) + f4);
        uint2 u1 = __ldg((const uint2*)(g_hh + (size_t)s1 * CH) + f4);
        uint2 u2 = __ldg((const uint2*)(g_hh + (size_t)s2 * CH) + f4);
        uint2 u3 = __ldg((const uint2*)(g_hh + (size_t)s3 * CH) + f4);
        acc_h4(acc, u0); acc_h4(acc, u1); acc_h4(acc, u2); acc_h4(acc, u3);
    }
    for (; i < cnt; i += 4) {
        int s = __ldg(g_eid1 + start + i);
        uint2 u = __ldg((const uint2*)(g_hh + (size_t)s * CH) + f4);
        acc_h4(acc, u);
    }
    #pragma unroll
    for (int o = 8; o <= 16; o <<= 1) {
        acc.x += __shfl_xor_sync(0xffffffffu, acc.x, o);
        acc.y += __shfl_xor_sync(0xffffffffu, acc.y, o);
        acc.z += __shfl_xor_sync(0xffffffffu, acc.z, o);
        acc.w += __shfl_xor_sync(0xffffffffu, acc.w, o);
    }

    float inv = 1.f / (float)max(cnt, 1);
    if (g == 0) {
        float4 r = __ldg((const float4*)(g_h + (size_t)row * CH) + f4);
        smean[w][f4 * 4 + 0] = acc.x * inv;
        smean[w][f4 * 4 + 1] = acc.y * inv;
        smean[w][f4 * 4 + 2] = acc.z * inv;
        smean[w][f4 * 4 + 3] = acc.w * inv;
        sroot[w][f4 * 4 + 0] = r.x;
        sroot[w][f4 * 4 + 1] = r.y;
        sroot[w][f4 * 4 + 2] = r.z;
        sroot[w][f4 * 4 + 3] = r.w;
    }
    __syncwarp();

    float v = __ldg(bl1 + lane);
    #pragma unroll
    for (int d = 0; d < CH; d++) {
        v = fmaf(smean[w][d], swl[lane * 33 + d], v);
        v = fmaf(sroot[w][d], swr[lane * 33 + d], v);
    }

    float s = v * v;
    #pragma unroll
    for (int o = 1; o < 32; o <<= 1)
        s += __shfl_xor_sync(0xffffffffu, s, o);
    float rinv = 1.f / fmaxf(sqrtf(s), CEPS);

    out[(size_t)row * CH + lane] = v * rinv;
}

// ============================================================
extern "C" void kernel_launch(void* const* d_in, const int* in_sizes, int n_in,
                              void* d_out, int out_size)
{
    const float* x    = (const float*)d_in[0];
    const int*   src0 = (const int*)d_in[1];
    const int*   tgt0 = (const int*)d_in[2];
    const int*   src1 = (const int*)d_in[3];
    const int*   tgt1 = (const int*)d_in[4];
    const float* wl0  = (const float*)d_in[5];
    const float* bl0  = (const float*)d_in[6];
    const float* wr0  = (const float*)d_in[7];
    const float* wl1  = (const float*)d_in[8];
    const float* bl1  = (const float*)d_in[9];
    const float* wr1  = (const float*)d_in[10];
    float* out = (float*)d_out;

    init_kernel<<<224, 256>>>(wl0, wr0);                              // 0
    histgemm_kernel<<<2048, 256>>>(tgt0, tgt1, x);                    // 1
    scan_both_kernel<<<192, 256>>>();                                 // 2
    bucket0gemm_kernel<<<2048, 256>>>(src0, tgt0, x);                 // 3 <- ncu
    aggfin0bucket1_kernel<<<512 * 33, 256>>>(src1, tgt1, bl0);        // 4
    aggfin1_kernel<<<CN2 / 8, 256>>>(bl1, wl1, wr1, out);             // 5
}

// round 17
// speedup vs baseline: 1.1373x; 1.1373x over previous
#include <cuda_runtime.h>
#include <cuda_bf16.h>
#include <cuda_fp16.h>

#define CN0 262144
#define CN1 131072
#define CN2 65536
#define CE0 2097152
#define CE1 1048576
#define CIN 128
#define CH  32
#define CEPS 1e-12f
#define BSTRIDE 68
#define CAP 64              // fixed per-target bucket capacity (mean deg 16, P(>64)~1e-20)

typedef unsigned int uint;

// ---- scratch (device globals; referenced from DEVICE code only) ----
__device__ float  g_r0[(size_t)CN1 * CH];     // x[:N1] @ wr0^T (fp32 root path)
__device__ float  g_h [(size_t)CN1 * CH];     // layer-0 out (fp32 root path)
__device__ __half g_y0h[(size_t)CN0 * CH];    // x @ wl0^T (fp16 gather table)
__device__ __half g_hh [(size_t)CN1 * CH];    // h (fp16 gather table)

__device__ __nv_bfloat16 g_whi[64 * CIN];
__device__ __nv_bfloat16 g_wlo[64 * CIN];

__device__ int g_cur0[CN1];                   // degree counters (= cnt after bucket)
__device__ int g_eid0[(size_t)CN1 * CAP];     // fixed-stride buckets (33 MB)
__device__ int g_cur1[CN2];
__device__ int g_eid1[(size_t)CN2 * CAP];     // 16 MB

__device__ __forceinline__ uint pkbf(float a, float b) {
    __nv_bfloat162 t = __halves2bfloat162(__float2bfloat16(a), __float2bfloat16(b));
    return *reinterpret_cast<uint*>(&t);
}
__device__ __forceinline__ void mma_bf16(float* d, const uint* a, uint b0, uint b1) {
    asm volatile(
        "mma.sync.aligned.m16n8k16.row.col.f32.bf16.bf16.f32 "
        "{%0,%1,%2,%3}, {%4,%5,%6,%7}, {%8,%9}, {%0,%1,%2,%3};"
        : "+f"(d[0]), "+f"(d[1]), "+f"(d[2]), "+f"(d[3])
        : "r"(a[0]), "r"(a[1]), "r"(a[2]), "r"(a[3]), "r"(b0), "r"(b1));
}
__device__ __forceinline__ void acc_h4(float4& acc, uint2 u) {
    __half2 h0 = *reinterpret_cast<__half2*>(&u.x);
    __half2 h1 = *reinterpret_cast<__half2*>(&u.y);
    float2 a = __half22float2(h0);
    float2 b = __half22float2(h1);
    acc.x += a.x; acc.y += a.y; acc.z += b.x; acc.w += b.y;
}

// ============================================================
// init: blocks [0,192) zero cur0/cur1, blocks [192,224) prep W.
// ============================================================
__global__ __launch_bounds__(256) void init_kernel(
    const float* __restrict__ wl0, const float* __restrict__ wr0)
{
    int blk = blockIdx.x;
    if (blk < 192) {
        int t = blk * 256 + threadIdx.x;          // 49152 int4 slots
        const int4 z = make_int4(0, 0, 0, 0);
        if (t < 32768) ((int4*)g_cur0)[t] = z;
        else           ((int4*)g_cur1)[t - 32768] = z;
    } else {
        int i = (blk - 192) * 256 + threadIdx.x;  // 8192 weights
        float v = (i < 32 * CIN) ? wl0[i] : wr0[i - 32 * CIN];
        __nv_bfloat16 h = __float2bfloat16(v);
        g_whi[i] = h;
        g_wlo[i] = __float2bfloat16(v - __bfloat162float(h));
    }
}

// ============================================================
// bucketgemm: role interleaved by blk%3 (grid 3072).
//   blk%3==2 -> bucket id blk/3 (1024 blocks x 3 chunks = 3072)
//   else     -> gemm tile (blk/3)*2 + blk%3  (2048 tiles)
// Fixed-capacity buckets: pos = cur[t]++; eid[t*CAP+pos] = src.
// ============================================================
__global__ __launch_bounds__(256) void bucketgemm_kernel(
    const int* __restrict__ src0, const int* __restrict__ tgt0,
    const int* __restrict__ src1, const int* __restrict__ tgt1,
    const float* __restrict__ x)
{
    __shared__ uint sbh[64 * BSTRIDE];
    __shared__ uint sbl[64 * BSTRIDE];

    int blk = blockIdx.x;
    int tid = threadIdx.x;

    if ((blk % 3) == 2) {
        // ---- bucket role ----
        int bi = blk / 3;                         // 0..1023
        #pragma unroll
        for (int j = 0; j < 3; j++) {
            int u = bi + j * 1024;                // 0..3071
            const int* src; const int* tgt;
            int* cur; int* eid;
            int eb;
            if (u < 2048) {
                src = src0; tgt = tgt0; cur = g_cur0; eid = g_eid0; eb = u;
            } else {
                src = src1; tgt = tgt1; cur = g_cur1; eid = g_eid1; eb = u - 2048;
            }
            int b = (eb * 256 + tid) * 4;
            int4 t = __ldg((const int4*)(tgt + b));
            int4 s = __ldg((const int4*)(src + b));
            int pos0 = atomicAdd(&cur[t.x], 1);
            int pos1 = atomicAdd(&cur[t.y], 1);
            int pos2 = atomicAdd(&cur[t.z], 1);
            int pos3 = atomicAdd(&cur[t.w], 1);
            eid[(size_t)t.x * CAP + pos0] = s.x;
            eid[(size_t)t.y * CAP + pos1] = s.y;
            eid[(size_t)t.z * CAP + pos2] = s.z;
            eid[(size_t)t.w * CAP + pos3] = s.w;
        }
        return;
    }

    // ---- gemm role ----
    int tile = (blk / 3) * 2 + (blk % 3);         // 0..2047
    int wid = tid >> 5, lane = tid & 31;
    {
        const uint* whi = (const uint*)g_whi;
        const uint* wlo = (const uint*)g_wlo;
        #pragma unroll
        for (int c = tid; c < 4096; c += 256) {
            int r = c >> 6, k = c & 63;
            sbh[r * BSTRIDE + k] = __ldg(whi + c);
            sbl[r * BSTRIDE + k] = __ldg(wlo + c);
        }
    }
    __syncthreads();

    int mrow = lane >> 2;
    int c = lane & 3;
    int nl = lane >> 2;

    int row0 = tile * 128 + wid * 16 + mrow;
    const float2* x2 = (const float2*)x;
    size_t base0 = (size_t)row0 * 64 + c;
    size_t base1 = base0 + 8 * 64;

    float d[8][4];
    #pragma unroll
    for (int n = 0; n < 8; n++)
        #pragma unroll
        for (int j = 0; j < 4; j++) d[n][j] = 0.f;

    #pragma unroll
    for (int ks = 0; ks < 8; ks++) {
        float2 p0 = __ldg(&x2[base0 + ks * 8]);
        float2 p1 = __ldg(&x2[base1 + ks * 8]);
        float2 p2 = __ldg(&x2[base0 + ks * 8 + 4]);
        float2 p3 = __ldg(&x2[base1 + ks * 8 + 4]);

        uint ah[4], al[4];
        ah[0] = pkbf(p0.x, p0.y);
        ah[1] = pkbf(p1.x, p1.y);
        ah[2] = pkbf(p2.x, p2.y);
        ah[3] = pkbf(p3.x, p3.y);
        {
            __nv_bfloat162 h0 = *(__nv_bfloat162*)&ah[0];
            __nv_bfloat162 h1 = *(__nv_bfloat162*)&ah[1];
            __nv_bfloat162 h2 = *(__nv_bfloat162*)&ah[2];
            __nv_bfloat162 h3 = *(__nv_bfloat162*)&ah[3];
            al[0] = pkbf(p0.x - __bfloat162float(h0.x), p0.y - __bfloat162float(h0.y));
            al[1] = pkbf(p1.x - __bfloat162float(h1.x), p1.y - __bfloat162float(h1.y));
            al[2] = pkbf(p2.x - __bfloat162float(h2.x), p2.y - __bfloat162float(h2.y));
            al[3] = pkbf(p3.x - __bfloat162float(h3.x), p3.y - __bfloat162float(h3.y));
        }

        #pragma unroll
        for (int n = 0; n < 8; n++) {
            int bidx = (n * 8 + nl) * BSTRIDE + ks * 8 + c;
            uint bh0 = sbh[bidx], bh1 = sbh[bidx + 4];
            uint bl0 = sbl[bidx], bl1 = sbl[bidx + 4];
            mma_bf16(d[n], ah, bh0, bh1);
            mma_bf16(d[n], al, bh0, bh1);
            mma_bf16(d[n], ah, bl0, bl1);
        }
    }

    int rA = row0;
    int rB = row0 + 8;
    #pragma unroll
    for (int n = 0; n < 8; n++) {
        int col = (n & 3) * 8 + c * 2;
        if (n < 4) {
            *(__half2*)(g_y0h + (size_t)rA * CH + col) = __floats2half2_rn(d[n][0], d[n][1]);
            *(__half2*)(g_y0h + (size_t)rB * CH + col) = __floats2half2_rn(d[n][2], d[n][3]);
        } else if (rA < CN1) {
            *(float2*)(g_r0 + (size_t)rA * CH + col) = make_float2(d[n][0], d[n][1]);
            *(float2*)(g_r0 + (size_t)rB * CH + col) = make_float2(d[n][2], d[n][3]);
        }
    }
}

// ============================================================
// aggfin0: warp per row; start = row*CAP, cnt = cur0[row].
// fp16 gather + fp32 mean + bl0 + r0 + L2norm + relu -> g_h, g_hh
// ============================================================
__global__ __launch_bounds__(256) void aggfin0_kernel(const float* __restrict__ bias)
{
    int lane = threadIdx.x & 31;
    int row = blockIdx.x * 8 + (threadIdx.x >> 5);
    int g = lane >> 3;
    int f4 = lane & 7;

    int cnt = __ldg(g_cur0 + row);
    const int* eptr = g_eid0 + (size_t)row * CAP;

    float4 acc = make_float4(0.f, 0.f, 0.f, 0.f);
    int i = g;
    for (; i + 12 < cnt; i += 16) {
        int s0 = __ldg(eptr + i);
        int s1 = __ldg(eptr + i + 4);
        int s2 = __ldg(eptr + i + 8);
        int s3 = __ldg(eptr + i + 12);
        uint2 u0 = __ldg((const uint2*)(g_y0h + (size_t)s0 * CH) + f4);
        uint2 u1 = __ldg((const uint2*)(g_y0h + (size_t)s1 * CH) + f4);
        uint2 u2 = __ldg((const uint2*)(g_y0h + (size_t)s2 * CH) + f4);
        uint2 u3 = __ldg((const uint2*)(g_y0h + (size_t)s3 * CH) + f4);
        acc_h4(acc, u0); acc_h4(acc, u1); acc_h4(acc, u2); acc_h4(acc, u3);
    }
    for (; i < cnt; i += 4) {
        int s = __ldg(eptr + i);
        uint2 u = __ldg((const uint2*)(g_y0h + (size_t)s * CH) + f4);
        acc_h4(acc, u);
    }
    #pragma unroll
    for (int o = 8; o <= 16; o <<= 1) {
        acc.x += __shfl_xor_sync(0xffffffffu, acc.x, o);
        acc.y += __shfl_xor_sync(0xffffffffu, acc.y, o);
        acc.z += __shfl_xor_sync(0xffffffffu, acc.z, o);
        acc.w += __shfl_xor_sync(0xffffffffu, acc.w, o);
    }

    float inv = 1.f / (float)max(cnt, 1);
    float4 b = __ldg((const float4*)bias + f4);
    float4 r = __ldg((const float4*)(g_r0 + (size_t)row * CH) + f4);

    float4 v;
    v.x = fmaf(acc.x, inv, b.x) + r.x;
    v.y = fmaf(acc.y, inv, b.y) + r.y;
    v.z = fmaf(acc.z, inv, b.z) + r.z;
    v.w = fmaf(acc.w, inv, b.w) + r.w;

    float s = v.x * v.x + v.y * v.y + v.z * v.z + v.w * v.w;
    s += __shfl_xor_sync(0xffffffffu, s, 1);
    s += __shfl_xor_sync(0xffffffffu, s, 2);
    s += __shfl_xor_sync(0xffffffffu, s, 4);
    float rinv = 1.f / fmaxf(sqrtf(s), CEPS);

    float4 o;
    o.x = fmaxf(v.x * rinv, 0.f);
    o.y = fmaxf(v.y * rinv, 0.f);
    o.z = fmaxf(v.z * rinv, 0.f);
    o.w = fmaxf(v.w * rinv, 0.f);
    if (g == 0) {
        ((float4*)(g_h + (size_t)row * CH))[f4] = o;
        uint2 hp;
        __half2 h0 = __floats2half2_rn(o.x, o.y);
        __half2 h1 = __floats2half2_rn(o.z, o.w);
        hp.x = *reinterpret_cast<uint*>(&h0);
        hp.y = *reinterpret_cast<uint*>(&h1);
        ((uint2*)(g_hh + (size_t)row * CH))[f4] = hp;
    }
}

// ============================================================
// aggfin1: warp per target row; fp16 gather of hh, fp32 root
// from g_h, per-lane matvec wl1/wr1, L2norm -> out
// ============================================================
__global__ __launch_bounds__(256) void aggfin1_kernel(
    const float* __restrict__ bl1,
    const float* __restrict__ wl1, const float* __restrict__ wr1,
    float* __restrict__ out)
{
    __shared__ float swl[CH * 33];
    __shared__ float swr[CH * 33];
    __shared__ float smean[8][CH];
    __shared__ float sroot[8][CH];

    int tid = threadIdx.x;
    for (int i = tid; i < CH * CH; i += 256) {
        int j = i >> 5, d = i & 31;
        swl[j * 33 + d] = __ldg(wl1 + i);
        swr[j * 33 + d] = __ldg(wr1 + i);
    }
    __syncthreads();

    int lane = tid & 31, w = tid >> 5;
    int row = blockIdx.x * 8 + w;
    int g = lane >> 3;
    int f4 = lane & 7;

    int cnt = __ldg(g_cur1 + row);
    const int* eptr = g_eid1 + (size_t)row * CAP;

    float4 acc = make_float4(0.f, 0.f, 0.f, 0.f);
    int i = g;
    for (; i + 12 < cnt; i += 16) {
        int s0 = __ldg(eptr + i);
        int s1 = __ldg(eptr + i + 4);
        int s2 = __ldg(eptr + i + 8);
        int s3 = __ldg(eptr + i + 12);
        uint2 u0 = __ldg((const uint2*)(g_hh + (size_t)s0 * CH) + f4);
        uint2 u1 = __ldg((const uint2*)(g_hh + (size_t)s1 * CH) + f4);
        uint2 u2 = __ldg((const uint2*)(g_hh + (size_t)s2 * CH) + f4);
        uint2 u3 = __ldg((const uint2*)(g_hh + (size_t)s3 * CH) + f4);
        acc_h4(acc, u0); acc_h4(acc, u1); acc_h4(acc, u2); acc_h4(acc, u3);
    }
    for (; i < cnt; i += 4) {
        int s = __ldg(eptr + i);
        uint2 u = __ldg((const uint2*)(g_hh + (size_t)s * CH) + f4);
        acc_h4(acc, u);
    }
    #pragma unroll
    for (int o = 8; o <= 16; o <<= 1) {
        acc.x += __shfl_xor_sync(0xffffffffu, acc.x, o);
        acc.y += __shfl_xor_sync(0xffffffffu, acc.y, o);
        acc.z += __shfl_xor_sync(0xffffffffu, acc.z, o);
        acc.w += __shfl_xor_sync(0xffffffffu, acc.w, o);
    }

    float inv = 1.f / (float)max(cnt, 1);
    if (g == 0) {
        float4 r = __ldg((const float4*)(g_h + (size_t)row * CH) + f4);
        smean[w][f4 * 4 + 0] = acc.x * inv;
        smean[w][f4 * 4 + 1] = acc.y * inv;
        smean[w][f4 * 4 + 2] = acc.z * inv;
        smean[w][f4 * 4 + 3] = acc.w * inv;
        sroot[w][f4 * 4 + 0] = r.x;
        sroot[w][f4 * 4 + 1] = r.y;
        sroot[w][f4 * 4 + 2] = r.z;
        sroot[w][f4 * 4 + 3] = r.w;
    }
    __syncwarp();

    float v = __ldg(bl1 + lane);
    #pragma unroll
    for (int d = 0; d < CH; d++) {
        v = fmaf(smean[w][d], swl[lane * 33 + d], v);
        v = fmaf(sroot[w][d], swr[lane * 33 + d], v);
    }

    float s = v * v;
    #pragma unroll
    for (int o = 1; o < 32; o <<= 1)
        s += __shfl_xor_sync(0xffffffffu, s, o);
    float rinv = 1.f / fmaxf(sqrtf(s), CEPS);

    out[(size_t)row * CH + lane] = v * rinv;
}

// ============================================================
extern "C" void kernel_launch(void* const* d_in, const int* in_sizes, int n_in,
                              void* d_out, int out_size)
{
    const float* x    = (const float*)d_in[0];
    const int*   src0 = (const int*)d_in[1];
    const int*   tgt0 = (const int*)d_in[2];
    const int*   src1 = (const int*)d_in[3];
    const int*   tgt1 = (const int*)d_in[4];
    const float* wl0  = (const float*)d_in[5];
    const float* bl0  = (const float*)d_in[6];
    const float* wr0  = (const float*)d_in[7];
    const float* wl1  = (const float*)d_in[8];
    const float* bl1  = (const float*)d_in[9];
    const float* wr1  = (const float*)d_in[10];
    float* out = (float*)d_out;

    init_kernel<<<224, 256>>>(wl0, wr0);                              // 0
    bucketgemm_kernel<<<3072, 256>>>(src0, tgt0, src1, tgt1, x);      // 1
    aggfin0_kernel<<<CN1 / 8, 256>>>(bl0);                            // 2
    aggfin1_kernel<<<CN2 / 8, 256>>>(bl1, wl1, wr1, out);             // 3 <- ncu
}